// round 1
// baseline (speedup 1.0000x reference)
#include <cuda_runtime.h>
#include <cuda_bf16.h>
#include <cstdint>

// Problem constants
#define BB 64
#define TT 1024
#define DD 512
#define BD (BB * DD)          // 32768
#define BTD ((size_t)BB * TT * DD)

// ---------------- scratch (no allocations allowed) ----------------
__device__ float g_xp[(size_t)TT * BB * DD];   // xproj, layout [t][b][e]
__device__ float g_m [(size_t)TT * BB * DD];   // m,     layout [t][b][e]
__device__ float g_tau[2][BD];                 // ping-pong tau state [b][e]
__device__ unsigned int g_count;               // grid barrier
__device__ unsigned int g_sense;               // grid barrier generation

// =====================================================================
// Kernel 1: fused precompute GEMM
//   out[r, n] = sum_k x[r,k] * W[n,k] + bias[n]
//   n <  512 : W = Wx  = tau_w[n, 0:512]   -> g_xp
//   n >= 512 : W = mem_w[n-512, :]         -> g_m
//   row r = b*T + t ; output written at [t][b][e]
// =====================================================================
__global__ void __launch_bounds__(256) pre_gemm(
    const float* __restrict__ x,
    const float* __restrict__ tau_w,
    const float* __restrict__ tau_b,
    const float* __restrict__ mem_w,
    const float* __restrict__ mem_b)
{
    constexpr int Bb = 128, Bn = 128, Bk = 16;
    __shared__ float As[Bk][Bb + 4];
    __shared__ float Bs[Bk][Bn + 4];

    const int tid = threadIdx.x;
    const int m0 = blockIdx.y * Bb;
    const int n0 = blockIdx.x * Bn;

    const float* wbase;
    const float* bias;
    int rstride;
    float* outg;
    if (n0 < 512) { wbase = tau_w + (size_t)n0 * 1024; rstride = 1024; bias = tau_b + n0; outg = g_xp; }
    else          { wbase = mem_w + (size_t)(n0 - 512) * 512; rstride = 512; bias = mem_b + (n0 - 512); outg = g_m; }

    const int tm = tid >> 4;     // 0..15
    const int tn = tid & 15;     // 0..15

    float acc[8][8];
#pragma unroll
    for (int i = 0; i < 8; i++)
#pragma unroll
        for (int j = 0; j < 8; j++) acc[i][j] = 0.0f;

    for (int kk = 0; kk < 512; kk += Bk) {
        // load A tile (128 rows x 16 k) and B tile (128 n-rows x 16 k), transposed into smem
#pragma unroll
        for (int u = 0; u < 2; u++) {
            int v   = tid + 256 * u;       // 0..511
            int row = v >> 2;              // 0..127
            int kc  = (v & 3) * 4;         // 0,4,8,12
            float4 a = *reinterpret_cast<const float4*>(&x[(size_t)(m0 + row) * 512 + kk + kc]);
            As[kc + 0][row] = a.x; As[kc + 1][row] = a.y; As[kc + 2][row] = a.z; As[kc + 3][row] = a.w;
            float4 b = *reinterpret_cast<const float4*>(&wbase[(size_t)row * rstride + kk + kc]);
            Bs[kc + 0][row] = b.x; Bs[kc + 1][row] = b.y; Bs[kc + 2][row] = b.z; Bs[kc + 3][row] = b.w;
        }
        __syncthreads();

#pragma unroll
        for (int k = 0; k < Bk; k++) {
            float af[8], bf[8];
            *reinterpret_cast<float4*>(&af[0]) = *reinterpret_cast<const float4*>(&As[k][tm * 8]);
            *reinterpret_cast<float4*>(&af[4]) = *reinterpret_cast<const float4*>(&As[k][tm * 8 + 4]);
            *reinterpret_cast<float4*>(&bf[0]) = *reinterpret_cast<const float4*>(&Bs[k][tn * 8]);
            *reinterpret_cast<float4*>(&bf[4]) = *reinterpret_cast<const float4*>(&Bs[k][tn * 8 + 4]);
#pragma unroll
            for (int i = 0; i < 8; i++)
#pragma unroll
                for (int j = 0; j < 8; j++)
                    acc[i][j] = fmaf(af[i], bf[j], acc[i][j]);
        }
        __syncthreads();
    }

    // epilogue: add bias, scatter to [t][b][e]
#pragma unroll
    for (int i = 0; i < 8; i++) {
        int r = m0 + tm * 8 + i;
        int b = r >> 10;
        int t = r & 1023;
        size_t rowoff = (size_t)t * BD + (size_t)b * DD;
#pragma unroll
        for (int j = 0; j < 8; j++) {
            int n = n0 + tn * 8 + j;
            outg[rowoff + (n & 511)] = acc[i][j] + bias[tn * 8 + j];
        }
    }
}

// =====================================================================
// Kernel 2: persistent scan kernel
// grid = 128 blocks (16 e-tiles x 8 b-tiles), 256 threads each,
// all co-resident -> custom grid barrier is safe.
//
// Compute phase: thread (kq=tid>>5, el=tid&31) holds Wt[e0+el, kq*64..+63]
// in registers, computes partial dot for 8 batches over its k-slice.
// Reduce via smem, then elementwise phase with thread (bl=tid>>5, el=tid&31)
// owning one (b,e) pair (v state lives in a register).
// =====================================================================
__device__ __forceinline__ void grid_barrier(unsigned int target)
{
    __threadfence();                 // each thread publishes its own writes
    __syncthreads();
    if (threadIdx.x == 0) {
        unsigned int a = atomicAdd(&g_count, 1);
        if (a == gridDim.x - 1) {
            g_count = 0;
            __threadfence();
            atomicAdd(&g_sense, 1);  // release generation
        } else {
            while (true) {
                unsigned int s = *((volatile unsigned int*)&g_sense);
                if ((int)(s - target) >= 0) break;
                __nanosleep(64);
            }
        }
        __threadfence();
    }
    __syncthreads();
}

__global__ void __launch_bounds__(256, 1) scan_kernel(
    const float* __restrict__ tau_w,
    const float* __restrict__ thr_p,
    float* __restrict__ out)
{
    __shared__ float tau_s[8 * 512];       // tau tile for 8 batches
    __shared__ float red_s[8 * 8 * 32];    // [kq][bl][el] partials

    const int tid = threadIdx.x;
    const int eb = blockIdx.x & 15;        // e-tile
    const int bb = blockIdx.x >> 4;        // b-tile
    const int e0 = eb * 32;
    const int b0 = bb * 8;

    // compute-phase mapping
    const int kq = tid >> 5;               // 0..7  (k slice)
    const int el = tid & 31;               // 0..31 (e within tile)
    const int e  = e0 + el;
    const int k0 = kq * 64;

    // load Wt[e, k0..k0+63] into registers (constant across all 1024 steps)
    float4 wv[16];
    {
        const float4* wrow = reinterpret_cast<const float4*>(tau_w + (size_t)e * 1024 + 512 + k0);
#pragma unroll
        for (int i = 0; i < 16; i++) wv[i] = wrow[i];
    }

    // elementwise-phase mapping: this thread owns (b2, e2)
    const int bl2 = tid >> 5;
    const int el2 = tid & 31;
    const int b2 = b0 + bl2;
    const int e2 = e0 + el2;

    float v = 0.0f;
    const float thr = *thr_p;

    float* out_spk = out;
    float* out_tau = out + BTD;
    float* out_v   = out + BTD + BD;

    // barrier generation base (stable: previous launch fully completed)
    unsigned int base = *((volatile unsigned int*)&g_sense);
    unsigned int bar = 0;

    // init tau0 = 1
    g_tau[0][b2 * DD + e2] = 1.0f;
    grid_barrier(base + (++bar));

    for (int t = 0; t < TT; t++) {
        const int cur = t & 1;
        const int nxt = cur ^ 1;

        // prefetch xp/m early (independent of tau)
        const size_t off = (size_t)t * BD + (size_t)b2 * DD + e2;
        const float xpv = g_xp[off];
        const float mv  = g_m[off];

        // stage tau for our 8 batches: 4096 floats = 1024 float4
        {
            const float4* src = reinterpret_cast<const float4*>(&g_tau[cur][b0 * DD]);
            float4* dst = reinterpret_cast<float4*>(tau_s);
#pragma unroll
            for (int i = 0; i < 4; i++) dst[tid + 256 * i] = src[tid + 256 * i];
        }
        __syncthreads();

        // partial dot products: 8 batches x 64 k per thread
        float acc[8];
#pragma unroll
        for (int bl = 0; bl < 8; bl++) acc[bl] = 0.0f;
#pragma unroll
        for (int jq = 0; jq < 16; jq++) {
            const float4 w4 = wv[jq];
#pragma unroll
            for (int bl = 0; bl < 8; bl++) {
                const float4 t4 = *reinterpret_cast<const float4*>(&tau_s[bl * 512 + k0 + jq * 4]);
                float a = acc[bl];
                a = fmaf(w4.x, t4.x, a);
                a = fmaf(w4.y, t4.y, a);
                a = fmaf(w4.z, t4.z, a);
                a = fmaf(w4.w, t4.w, a);
                acc[bl] = a;
            }
        }

        // k-split reduction through smem
#pragma unroll
        for (int bl = 0; bl < 8; bl++) red_s[kq * 256 + bl * 32 + el] = acc[bl];
        __syncthreads();

        float z = xpv;
#pragma unroll
        for (int q = 0; q < 8; q++) z += red_s[q * 256 + bl2 * 32 + el2];

        // tau' = sigmoid(z) ; alpha = exp(-1/(tau'+1e-6))
        const float ta = 1.0f / (1.0f + expf(-z));
        const float al = expf(-1.0f / (ta + 1e-6f));
        v = al * v + (1.0f - al) * mv;
        const float s = (v >= thr) ? 1.0f : 0.0f;
        out_spk[(size_t)b2 * TT * DD + (size_t)t * DD + e2] = s;
        v = v * (1.0f - s);

        g_tau[nxt][b2 * DD + e2] = ta;
        if (t == TT - 1) {
            out_tau[b2 * DD + e2] = ta;
            out_v[b2 * DD + e2]   = v;
        }

        grid_barrier(base + (++bar));
    }
}

// =====================================================================
extern "C" void kernel_launch(void* const* d_in, const int* in_sizes, int n_in,
                              void* d_out, int out_size)
{
    const float* x     = (const float*)d_in[0];
    const float* tau_w = (const float*)d_in[1];
    const float* tau_b = (const float*)d_in[2];
    const float* mem_w = (const float*)d_in[3];
    const float* mem_b = (const float*)d_in[4];
    const float* thr   = (const float*)d_in[5];
    float* out = (float*)d_out;

    dim3 ggrid(8, 512);                 // N tiles x M tiles
    pre_gemm<<<ggrid, 256>>>(x, tau_w, tau_b, mem_w, mem_b);
    scan_kernel<<<128, 256>>>(tau_w, thr, out);
}

// round 2
// speedup vs baseline: 1.0583x; 1.0583x over previous
#include <cuda_runtime.h>
#include <cuda_bf16.h>
#include <cstdint>

// Problem constants
#define BB 64
#define TT 1024
#define DD 512
#define BD (BB * DD)          // 32768
#define BTD ((size_t)BB * TT * DD)

// ---------------- scratch (no allocations allowed) ----------------
__device__ float g_xp[(size_t)TT * BB * DD];   // xproj, layout [t][b][e]
__device__ float g_m [(size_t)TT * BB * DD];   // m,     layout [t][b][e]
__device__ float g_tau[2][BD];                 // ping-pong tau state [b][e]
__device__ unsigned int g_count;               // grid barrier
__device__ unsigned int g_sense;               // grid barrier generation

// ---------------- f32x2 packed-FMA helpers ----------------
__device__ __forceinline__ unsigned long long fma2(unsigned long long a,
                                                   unsigned long long b,
                                                   unsigned long long c)
{
    unsigned long long d;
    asm("fma.rn.f32x2 %0, %1, %2, %3;" : "=l"(d) : "l"(a), "l"(b), "l"(c));
    return d;
}
__device__ __forceinline__ unsigned long long pack2(float lo, float hi)
{
    unsigned long long r;
    asm("mov.b64 %0, {%1, %2};" : "=l"(r) : "f"(lo), "f"(hi));
    return r;
}
__device__ __forceinline__ float2 unpack2(unsigned long long v)
{
    float2 f;
    asm("mov.b64 {%0, %1}, %2;" : "=f"(f.x), "=f"(f.y) : "l"(v));
    return f;
}

// =====================================================================
// Kernel 1: fused precompute GEMM (FFMA2 inner product)
//   out[r, n] = sum_k x[r,k] * W[n,k] + bias[n]
//   n <  512 : W = Wx  = tau_w[n, 0:512]   -> g_xp
//   n >= 512 : W = mem_w[n-512, :]         -> g_m
//   row r = b*T + t ; output written at [t][b][e]
// =====================================================================
__global__ void __launch_bounds__(256, 2) pre_gemm(
    const float* __restrict__ x,
    const float* __restrict__ tau_w,
    const float* __restrict__ tau_b,
    const float* __restrict__ mem_w,
    const float* __restrict__ mem_b)
{
    constexpr int Bb = 128, Bn = 128, Bk = 16;
    __shared__ float As[Bk][Bb + 4];
    __shared__ float Bs[Bk][Bn + 4];

    const int tid = threadIdx.x;
    const int m0 = blockIdx.y * Bb;
    const int n0 = blockIdx.x * Bn;

    const float* wbase;
    const float* bias;
    int rstride;
    float* outg;
    if (n0 < 512) { wbase = tau_w + (size_t)n0 * 1024; rstride = 1024; bias = tau_b + n0; outg = g_xp; }
    else          { wbase = mem_w + (size_t)(n0 - 512) * 512; rstride = 512; bias = mem_b + (n0 - 512); outg = g_m; }

    const int tm = tid >> 4;     // 0..15
    const int tn = tid & 15;     // 0..15

    unsigned long long acc2[8][4];   // 8 i-rows x 4 f32x2 pairs (8 j-cols)
#pragma unroll
    for (int i = 0; i < 8; i++)
#pragma unroll
        for (int p = 0; p < 4; p++) acc2[i][p] = 0ULL;

    for (int kk = 0; kk < 512; kk += Bk) {
        // load A tile (128 rows x 16 k) and B tile (128 n-rows x 16 k), transposed into smem
#pragma unroll
        for (int u = 0; u < 2; u++) {
            int v   = tid + 256 * u;       // 0..511
            int row = v >> 2;              // 0..127
            int kc  = (v & 3) * 4;         // 0,4,8,12
            float4 a = *reinterpret_cast<const float4*>(&x[(size_t)(m0 + row) * 512 + kk + kc]);
            As[kc + 0][row] = a.x; As[kc + 1][row] = a.y; As[kc + 2][row] = a.z; As[kc + 3][row] = a.w;
            float4 b = *reinterpret_cast<const float4*>(&wbase[(size_t)row * rstride + kk + kc]);
            Bs[kc + 0][row] = b.x; Bs[kc + 1][row] = b.y; Bs[kc + 2][row] = b.z; Bs[kc + 3][row] = b.w;
        }
        __syncthreads();

#pragma unroll
        for (int k = 0; k < Bk; k++) {
            float af[8];
            *reinterpret_cast<float4*>(&af[0]) = *reinterpret_cast<const float4*>(&As[k][tm * 8]);
            *reinterpret_cast<float4*>(&af[4]) = *reinterpret_cast<const float4*>(&As[k][tm * 8 + 4]);
            ulonglong2 b01 = *reinterpret_cast<const ulonglong2*>(&Bs[k][tn * 8]);
            ulonglong2 b23 = *reinterpret_cast<const ulonglong2*>(&Bs[k][tn * 8 + 4]);
#pragma unroll
            for (int i = 0; i < 8; i++) {
                unsigned long long a2 = pack2(af[i], af[i]);
                acc2[i][0] = fma2(a2, b01.x, acc2[i][0]);
                acc2[i][1] = fma2(a2, b01.y, acc2[i][1]);
                acc2[i][2] = fma2(a2, b23.x, acc2[i][2]);
                acc2[i][3] = fma2(a2, b23.y, acc2[i][3]);
            }
        }
        __syncthreads();
    }

    // epilogue: add bias, scatter to [t][b][e]
#pragma unroll
    for (int i = 0; i < 8; i++) {
        int r = m0 + tm * 8 + i;
        int b = r >> 10;
        int t = r & 1023;
        size_t rowoff = (size_t)t * BD + (size_t)b * DD;
#pragma unroll
        for (int p = 0; p < 4; p++) {
            float2 f = unpack2(acc2[i][p]);
            int n  = n0 + tn * 8 + 2 * p;
            outg[rowoff + ((n + 0) & 511)] = f.x + bias[tn * 8 + 2 * p + 0];
            outg[rowoff + ((n + 1) & 511)] = f.y + bias[tn * 8 + 2 * p + 1];
        }
    }
}

// =====================================================================
// Kernel 2: persistent scan kernel
// grid = 128 blocks (16 e-tiles x 8 b-tiles), 256 threads each.
// Cross-block tau state is accessed with .cg (L2-coherent) so correctness
// does not depend on L1; fences live in thread 0 only (CG-style barrier:
// bar.sync cumulativity + thread-0 release/acquire).
// =====================================================================
__device__ __forceinline__ void grid_barrier(unsigned int target)
{
    __syncthreads();
    if (threadIdx.x == 0) {
        __threadfence();                 // release: order block's writes before arrival
        unsigned int a = atomicAdd(&g_count, 1);
        if (a == gridDim.x - 1) {
            g_count = 0;
            __threadfence();
            atomicAdd(&g_sense, 1);      // release generation
        } else {
            unsigned int s;
            do {
                asm volatile("ld.acquire.gpu.u32 %0, [%1];" : "=r"(s) : "l"(&g_sense));
            } while ((int)(s - target) < 0);
        }
        __threadfence();                 // acquire: invalidate this SM's L1
    }
    __syncthreads();
}

__global__ void __launch_bounds__(256, 1) scan_kernel(
    const float* __restrict__ tau_w,
    const float* __restrict__ thr_p,
    float* __restrict__ out)
{
    __shared__ float tau_s[8 * 512];       // tau tile for 8 batches
    __shared__ float red_s[8 * 8 * 32];    // [kq][bl][el] partials

    const int tid = threadIdx.x;
    const int eb = blockIdx.x & 15;        // e-tile
    const int bb = blockIdx.x >> 4;        // b-tile
    const int e0 = eb * 32;
    const int b0 = bb * 8;

    // compute-phase mapping
    const int kq = tid >> 5;               // 0..7  (k slice)
    const int el = tid & 31;               // 0..31 (e within tile)
    const int e  = e0 + el;
    const int k0 = kq * 64;

    // load Wt[e, k0..k0+63] into registers as f32x2 pairs (constant over steps)
    ulonglong2 wv2[16];
    {
        const ulonglong2* wrow = reinterpret_cast<const ulonglong2*>(tau_w + (size_t)e * 1024 + 512 + k0);
#pragma unroll
        for (int i = 0; i < 16; i++) wv2[i] = wrow[i];
    }

    // elementwise-phase mapping: this thread owns (b2, e2)
    const int bl2 = tid >> 5;
    const int el2 = tid & 31;
    const int b2 = b0 + bl2;
    const int e2 = e0 + el2;

    float v = 0.0f;
    const float thr = *thr_p;

    float* out_spk = out;
    float* out_tau = out + BTD;
    float* out_v   = out + BTD + BD;

    // barrier generation base (stable: previous launch fully completed)
    unsigned int base;
    asm volatile("ld.acquire.gpu.u32 %0, [%1];" : "=r"(base) : "l"(&g_sense));
    unsigned int bar = 0;

    // init tau0 = 1
    __stcg(&g_tau[0][b2 * DD + e2], 1.0f);
    grid_barrier(base + (++bar));

    for (int t = 0; t < TT; t++) {
        const int cur = t & 1;
        const int nxt = cur ^ 1;

        // prefetch xp/m early (independent of tau)
        const size_t off = (size_t)t * BD + (size_t)b2 * DD + e2;
        const float xpv = __ldcs(&g_xp[off]);
        const float mv  = __ldcs(&g_m[off]);

        // stage tau for our 8 batches: 4096 floats = 1024 float4 (L2-coherent loads)
        {
            const float4* src = reinterpret_cast<const float4*>(&g_tau[cur][b0 * DD]);
            float4* dst = reinterpret_cast<float4*>(tau_s);
#pragma unroll
            for (int i = 0; i < 4; i++) dst[tid + 256 * i] = __ldcg(src + tid + 256 * i);
        }
        __syncthreads();

        // partial dot products: 8 batches x 64 k per thread, packed f32x2
        unsigned long long acc2[8];
#pragma unroll
        for (int bl = 0; bl < 8; bl++) acc2[bl] = 0ULL;
#pragma unroll
        for (int jq = 0; jq < 16; jq++) {
            const ulonglong2 w2 = wv2[jq];
#pragma unroll
            for (int bl = 0; bl < 8; bl++) {
                const ulonglong2 t2 = *reinterpret_cast<const ulonglong2*>(&tau_s[bl * 512 + k0 + jq * 4]);
                acc2[bl] = fma2(w2.x, t2.x, acc2[bl]);
                acc2[bl] = fma2(w2.y, t2.y, acc2[bl]);
            }
        }

        // k-split reduction through smem
#pragma unroll
        for (int bl = 0; bl < 8; bl++) {
            float2 f = unpack2(acc2[bl]);
            red_s[kq * 256 + bl * 32 + el] = f.x + f.y;
        }
        __syncthreads();

        float z = xpv;
#pragma unroll
        for (int q = 0; q < 8; q++) z += red_s[q * 256 + bl2 * 32 + el2];

        // tau' = sigmoid(z) ; alpha = exp(-1/(tau'+1e-6))
        const float ta = 1.0f / (1.0f + expf(-z));
        const float al = expf(-1.0f / (ta + 1e-6f));
        v = al * v + (1.0f - al) * mv;
        const float s = (v >= thr) ? 1.0f : 0.0f;
        __stcs(&out_spk[(size_t)b2 * TT * DD + (size_t)t * DD + e2], s);
        v = v * (1.0f - s);

        __stcg(&g_tau[nxt][b2 * DD + e2], ta);
        if (t == TT - 1) {
            out_tau[b2 * DD + e2] = ta;
            out_v[b2 * DD + e2]   = v;
        }

        grid_barrier(base + (++bar));
    }
}

// =====================================================================
extern "C" void kernel_launch(void* const* d_in, const int* in_sizes, int n_in,
                              void* d_out, int out_size)
{
    const float* x     = (const float*)d_in[0];
    const float* tau_w = (const float*)d_in[1];
    const float* tau_b = (const float*)d_in[2];
    const float* mem_w = (const float*)d_in[3];
    const float* mem_b = (const float*)d_in[4];
    const float* thr   = (const float*)d_in[5];
    float* out = (float*)d_out;

    dim3 ggrid(8, 512);                 // N tiles x M tiles
    pre_gemm<<<ggrid, 256>>>(x, tau_w, tau_b, mem_w, mem_b);
    scan_kernel<<<128, 256>>>(tau_w, thr, out);
}